// round 17
// baseline (speedup 1.0000x reference)
#include <cuda_runtime.h>
#include <cuda_fp16.h>
#include <cstdint>
#include <cstddef>

// ============================================================================
// ComplexMixture, single fused kernel. mma.sync fp16 (11-bit mantissa = tf32).
// G = X^T X per batch, X = [R | I] (S x 128); symmetric -> 10 upper 32x32
// warp tiles. K split across 9 CTAs/batch (grid 288). Compact per-tile
// scratch; the last-arriving CTA per batch reduces the 9 partials (fixed
// order -> deterministic) and writes both outputs. One kernel launch total.
// ============================================================================

namespace {
constexpr int kB = 32;
constexpr int kS = 8192;
constexpr int kD = 64;
constexpr int kM = 128;                   // 2*D
constexpr int kSplit = 9;
constexpr int kBK = 32;                   // K rows per stage
constexpr int kRowB = 272;                // bytes/row: 256 data + 16 pad
constexpr int kStageB = kBK * kRowB;      // 8704
constexpr int kTileF = 32 * 32;           // floats per tile
}  // namespace

// Compact partial scratch: [B][SPLIT][10 tiles][32][32] f32 (~11.8 MB)
__device__ float g_scratch[(size_t)kB * kSplit * 10 * kTileF];
__device__ int g_ctr[kB];  // zero-init; reducer resets -> replay-safe

__device__ __forceinline__ uint32_t smem_u32(const void* p) {
    uint32_t a;
    asm("{ .reg .u64 t; cvta.to.shared.u64 t, %1; cvt.u32.u64 %0, t; }"
        : "=r"(a) : "l"(p));
    return a;
}
__device__ __forceinline__ void ldsm_x4_t(uint32_t addr, uint32_t* r) {
    asm volatile(
        "ldmatrix.sync.aligned.m8n8.x4.trans.shared.b16 {%0,%1,%2,%3}, [%4];"
        : "=r"(r[0]), "=r"(r[1]), "=r"(r[2]), "=r"(r[3]) : "r"(addr));
}
__device__ __forceinline__ void mma_f16(float* d, const uint32_t* a,
                                        const uint32_t* b0, const uint32_t* b1) {
    asm volatile(
        "mma.sync.aligned.m16n8k16.row.col.f32.f16.f16.f32 "
        "{%0,%1,%2,%3}, {%4,%5,%6,%7}, {%8,%9}, {%0,%1,%2,%3};"
        : "+f"(d[0]), "+f"(d[1]), "+f"(d[2]), "+f"(d[3])
        : "r"(a[0]), "r"(a[1]), "r"(a[2]), "r"(a[3]), "r"(*b0), "r"(*b1));
}
__device__ __forceinline__ void sts_f4h(uint32_t addr, float4 v) {
    __half2 lo = __floats2half2_rn(v.x, v.y);
    __half2 hi = __floats2half2_rn(v.z, v.w);
    asm volatile("st.shared.v2.b32 [%0], {%1, %2};"
                 :: "r"(addr),
                    "r"(*reinterpret_cast<uint32_t*>(&lo)),
                    "r"(*reinterpret_cast<uint32_t*>(&hi)) : "memory");
}
// Upper-triangle tile slot for ti<=tj over 4x4 blocks.
__device__ __forceinline__ int slot_of(int ti, int tj) {
    return ti * 4 - ((ti * (ti + 1)) >> 1) + tj;
}

union SmemU {
    char pipe[2 * kStageB];        // mainloop double buffer (17408 B)
    float tiles[10][32][33];       // reducer staging (42240 B)
};

// ---------------------------------------------------------------------------
// Fused kernel: per-(batch, split) partial Gram; last CTA per batch reduces.
// 320 threads = 10 warps; warp w owns upper 32x32 tile slot w.
// Warps 0..7 are loaders (4 smem rows each per stage). 2 CTAs/SM.
// ---------------------------------------------------------------------------
__global__ void __launch_bounds__(320, 2)
gram_kernel(const float* __restrict__ xr, const float* __restrict__ xi,
            float* __restrict__ out) {
    __shared__ __align__(16) SmemU sm;
    __shared__ int is_red;

    const int t = threadIdx.x;
    const int wid = t >> 5;
    const int lane = t & 31;
    const int b = blockIdx.x / kSplit;
    const int p = blockIdx.x - b * kSplit;

    // Deterministic uneven K partition: splits 0..3 get 29 iters, 4..8 get 28.
    const int it0 = p * 28 + (p < 4 ? p : 4);
    const int niter = 28 + (p < 4 ? 1 : 0);

    const int ti_tab[10] = {0, 0, 0, 0, 1, 1, 1, 2, 2, 3};
    const int tj_tab[10] = {0, 1, 2, 3, 1, 2, 3, 2, 3, 3};
    const int ti = ti_tab[wid];
    const int tj = tj_tab[wid];

    float acc[2][4][4];
#pragma unroll
    for (int mt = 0; mt < 2; ++mt)
#pragma unroll
        for (int nt = 0; nt < 4; ++nt)
#pragma unroll
            for (int e = 0; e < 4; ++e) acc[mt][nt][e] = 0.0f;

    const uint32_t smem0 = smem_u32(sm.pipe);

    // ldmatrix.x4.trans lane offsets (bytes within a stage buffer).
    const int g = lane >> 3;
    const int lr = lane & 7;
    uint32_t aoff[2], boff[2];
#pragma unroll
    for (int mt = 0; mt < 2; ++mt) {
        const int r0 = ti * 32 + mt * 16;
        aoff[mt] = (uint32_t)((lr + ((g >= 2) ? 8 : 0)) * kRowB + r0 * 2 +
                              ((g & 1) ? 16 : 0));
    }
#pragma unroll
    for (int np = 0; np < 2; ++np) {
        const int c0 = tj * 32 + np * 16;
        boff[np] = (uint32_t)((lr + ((g & 1) ? 8 : 0)) * kRowB + c0 * 2 +
                              ((g >= 2) ? 16 : 0));
    }

    // Loader mapping: warp w (0..7) owns smem rows w*4..w*4+3 per stage.
    // Lanes 0-15: xr (m 0..63), lanes 16-31: xi (m 64..127); float4 each.
    const bool loader = (wid < 8);
    const int half_sel = lane >> 4;
    const int li = lane & 15;
    const float* src = half_sel ? xi : xr;
    const size_t gbase =
        ((size_t)b * kS + (size_t)(it0 * kBK) + (size_t)(wid * 4)) * kD +
        (size_t)(4 * li);
    const uint32_t sts_off =
        (uint32_t)(wid * 4 * kRowB + half_sel * 128 + li * 8);

    float4 cur[4], nxt[4];
    if (loader) {
        // Stage 0 -> buf 0; prefetch stage 1 into regs.
#pragma unroll
        for (int j = 0; j < 4; ++j) {
            const float4 v =
                *reinterpret_cast<const float4*>(src + gbase + (size_t)j * kD);
            sts_f4h(smem0 + sts_off + (uint32_t)(j * kRowB), v);
        }
        if (niter > 1) {
#pragma unroll
            for (int j = 0; j < 4; ++j)
                cur[j] = *reinterpret_cast<const float4*>(src + gbase +
                                                          (size_t)(32 + j) * kD);
        }
    }

    for (int it = 0; it < niter; ++it) {
        const int s = it & 1;
        __syncthreads();  // buf[s] ready; buf[s^1] free

        if (loader) {
            // LDG first (enter memory system early), then STS from cur regs.
            if (it + 2 < niter) {
                const size_t goff = gbase + (size_t)((it + 2) * kBK) * kD;
#pragma unroll
                for (int j = 0; j < 4; ++j)
                    nxt[j] = *reinterpret_cast<const float4*>(src + goff +
                                                              (size_t)j * kD);
            }
            if (it + 1 < niter) {
                const uint32_t dst =
                    smem0 + (uint32_t)((s ^ 1) * kStageB) + sts_off;
#pragma unroll
                for (int j = 0; j < 4; ++j)
                    sts_f4h(dst + (uint32_t)(j * kRowB), cur[j]);
            }
#pragma unroll
            for (int j = 0; j < 4; ++j) cur[j] = nxt[j];
        }

        const uint32_t sb = smem0 + (uint32_t)(s * kStageB);
#pragma unroll
        for (int ks = 0; ks < 2; ++ks) {
            const uint32_t ko = (uint32_t)(ks * 16 * kRowB);
            uint32_t A0[4], A1[4], B0[4], B1[4];
            ldsm_x4_t(sb + ko + aoff[0], A0);
            ldsm_x4_t(sb + ko + aoff[1], A1);
            ldsm_x4_t(sb + ko + boff[0], B0);
            ldsm_x4_t(sb + ko + boff[1], B1);
            mma_f16(acc[0][0], A0, B0 + 0, B0 + 1);
            mma_f16(acc[0][1], A0, B0 + 2, B0 + 3);
            mma_f16(acc[0][2], A0, B1 + 0, B1 + 1);
            mma_f16(acc[0][3], A0, B1 + 2, B1 + 3);
            mma_f16(acc[1][0], A1, B0 + 0, B0 + 1);
            mma_f16(acc[1][1], A1, B0 + 2, B0 + 3);
            mma_f16(acc[1][2], A1, B1 + 0, B1 + 1);
            mma_f16(acc[1][3], A1, B1 + 2, B1 + 3);
        }
    }

    // Write this warp's 32x32 tile to compact scratch (contiguous per tile).
    const int fr = lane >> 2;
    const int fc = lane & 3;
    float* scr = g_scratch +
                 (((size_t)(b * kSplit + p)) * 10 + (size_t)wid) * kTileF;
#pragma unroll
    for (int mt = 0; mt < 2; ++mt) {
#pragma unroll
        for (int nt = 0; nt < 4; ++nt) {
            const int row = mt * 16 + fr;
            const int col = nt * 8 + 2 * fc;
            float2 v0 = make_float2(acc[mt][nt][0], acc[mt][nt][1]);
            float2 v1 = make_float2(acc[mt][nt][2], acc[mt][nt][3]);
            *reinterpret_cast<float2*>(scr + row * 32 + col) = v0;
            *reinterpret_cast<float2*>(scr + (row + 8) * 32 + col) = v1;
        }
    }

    // ---------------- last-CTA-per-batch reduction + output ----------------
    __threadfence();   // make this thread's scratch stores globally visible
    __syncthreads();
    if (t == 0) {
        const int old = atomicAdd(&g_ctr[b], 1);
        is_red = (old == kSplit - 1);
        if (is_red) atomicExch(&g_ctr[b], 0);  // reset for next graph replay
    }
    __syncthreads();
    if (!is_red) return;
    __threadfence();   // acquire: see all other CTAs' scratch stores

    // Sum the 9 partials into padded smem tiles (fixed order: deterministic).
    // 10 tiles * 256 float4 = 2560 float4; 320 threads * 8 iterations.
    const float* base = g_scratch + (size_t)b * kSplit * 10 * kTileF;
#pragma unroll
    for (int v = 0; v < 8; ++v) {
        const int f = v * 320 + t;          // float4 index, coalesced
        const int slot = f >> 8;
        const int q = f & 255;              // float4 within tile
        const float* src4 = base + (size_t)slot * kTileF + (size_t)(q * 4);
        float4 s0 = make_float4(0.f, 0.f, 0.f, 0.f);
        float4 s1 = make_float4(0.f, 0.f, 0.f, 0.f);
#pragma unroll
        for (int pp = 0; pp < 5; ++pp) {
            const float4 w = *reinterpret_cast<const float4*>(
                src4 + (size_t)pp * 10 * kTileF);
            s0.x += w.x; s0.y += w.y; s0.z += w.z; s0.w += w.w;
        }
#pragma unroll
        for (int pp = 5; pp < kSplit; ++pp) {
            const float4 w = *reinterpret_cast<const float4*>(
                src4 + (size_t)pp * 10 * kTileF);
            s1.x += w.x; s1.y += w.y; s1.z += w.z; s1.w += w.w;
        }
        const int r = q >> 3;
        const int c4 = (q & 7) * 4;
        sm.tiles[slot][r][c4 + 0] = s0.x + s1.x;
        sm.tiles[slot][r][c4 + 1] = s0.y + s1.y;
        sm.tiles[slot][r][c4 + 2] = s0.z + s1.z;
        sm.tiles[slot][r][c4 + 3] = s0.w + s1.w;
    }
    __syncthreads();

    // Combine -> outputs (256 threads, float4-coalesced writes).
    if (t >= 256) return;
    const float invS = 1.0f / (float)kS;
    float* out_r = out + (size_t)b * kD * kD;
    float* out_i = out + (size_t)kB * kD * kD + (size_t)b * kD * kD;
#pragma unroll
    for (int v = 0; v < 4; ++v) {
        const int idx = v * 1024 + t * 4;
        const int i = idx >> 6;
        const int j0 = idx & 63;
        float rr[4], im[4];
#pragma unroll
        for (int u = 0; u < 4; ++u) {
            const int j = j0 + u;
            // real: (G(i,j) + G(64+i,64+j)) / S, mirror into upper triangle
            const int ii = (i <= j) ? i : j;
            const int jj = (i <= j) ? j : i;
            const int bi = ii >> 5, bj = jj >> 5;
            rr[u] = (sm.tiles[slot_of(bi, bj)][ii & 31][jj & 31] +
                     sm.tiles[slot_of(bi + 2, bj + 2)][ii & 31][jj & 31]) *
                    invS;
            // imag: (G01[i][j] - G01[j][i]) / S (block 01 tiles all computed)
            const float a =
                sm.tiles[slot_of(i >> 5, 2 + (j >> 5))][i & 31][j & 31];
            const float c =
                sm.tiles[slot_of(j >> 5, 2 + (i >> 5))][j & 31][i & 31];
            im[u] = (a - c) * invS;
        }
        *reinterpret_cast<float4*>(out_r + idx) =
            make_float4(rr[0], rr[1], rr[2], rr[3]);
        *reinterpret_cast<float4*>(out_i + idx) =
            make_float4(im[0], im[1], im[2], im[3]);
    }
}

// ---------------------------------------------------------------------------
extern "C" void kernel_launch(void* const* d_in, const int* in_sizes, int n_in,
                              void* d_out, int out_size) {
    const float* xr = (const float*)d_in[0];
    const float* xi = (const float*)d_in[1];
    float* out = (float*)d_out;

    gram_kernel<<<kB * kSplit, 320>>>(xr, xi, out);
}